// round 1
// baseline (speedup 1.0000x reference)
#include <cuda_runtime.h>
#include <math.h>

// IAF with 2 MADE flows, B=4096, D=H=64.
// Key identity: the reference's forward lax.scan computes the EXACT inverse of
// z -> z - made_shift(z) (strict autoregressiveness => converges in D steps),
// so u_final == z_mean + exp(0.5*lv)*eps and
// density = -0.5*D*log(2pi) - 0.5*sum(lv) - 0.5*sum(eps^2).
// Only the inverse pass (2 masked MLP evals) needs real compute.

#define RB  32      // rows (batch elements) per block
#define NT  512     // 16 threads per row, 4 outputs per thread
#define XST 68      // padded row stride in shared (64 + 4, avoids bank conflicts)

__global__ __launch_bounds__(NT, 1)
void iaf_kernel(const float* __restrict__ zm, const float* __restrict__ lvp,
                const float* __restrict__ ep,
                const float* __restrict__ W0, const float* __restrict__ b0,
                const float* __restrict__ W1, const float* __restrict__ b1,
                const float* __restrict__ W2, const float* __restrict__ b2,
                const float* __restrict__ Wo, const float* __restrict__ bo,
                float* __restrict__ out, int B)
{
    extern __shared__ float sm[];
    float* wts = sm;                    // 8 matrices * 4096 floats (flow-major: f*4+layer)
    float* bss = wts + 8 * 4096;        // 8 * 64 biases
    float* Xs  = bss + 8 * 64;          // RB x XST  (current z per row)
    float* Ha  = Xs + RB * XST;         // hidden ping
    float* Hb  = Ha + RB * XST;         // hidden pong

    const int tid = threadIdx.x;

    // ---- Load weights once per block, pre-multiplying the MADE masks.
    // d_h[h] = h % 63 + 1 (D=H=64). Store dh-1 = h%63.
    for (int idx = tid; idx < 2 * 4096; idx += NT) {
        int e   = idx & 4095;
        int f   = idx >> 12;            // flow index 0/1
        int row = e >> 6;               // input index of the matrix
        int col = e & 63;               // output index of the matrix
        int dhc = col % 63;             // d_h(col) - 1
        int dhr = row % 63;             // d_h(row) - 1
        float w0 = W0[idx], w1 = W1[idx], w2 = W2[idx], wo = Wo[idx];
        // m_in[d][h]  : d+1 <= d_h[h]      <=> row <= dhc
        // m_hid[k][j] : d_h[k] <= d_h[j]   <=> dhr <= dhc
        // m_out[h][d] : d_h[h] < d+1       <=> dhr < col
        wts[(f * 4 + 0) * 4096 + e] = (row <= dhc) ? w0 : 0.0f;
        wts[(f * 4 + 1) * 4096 + e] = (dhr <= dhc) ? w1 : 0.0f;
        wts[(f * 4 + 2) * 4096 + e] = (dhr <= dhc) ? w2 : 0.0f;
        wts[(f * 4 + 3) * 4096 + e] = (dhr <  col) ? wo : 0.0f;
    }
    for (int idx = tid; idx < 2 * 64; idx += NT) {
        int f = idx >> 6, j = idx & 63;
        bss[(f * 4 + 0) * 64 + j] = b0[idx];
        bss[(f * 4 + 1) * 64 + j] = b1[idx];
        bss[(f * 4 + 2) * 64 + j] = b2[idx];
        bss[(f * 4 + 3) * 64 + j] = bo[idx];
    }

    const int r    = tid >> 4;          // row within block (0..31)
    const int c    = tid & 15;          // 16 threads per row
    const int j0   = c << 2;            // 4 consecutive outputs per thread
    const int grow = blockIdx.x * RB + r;
    const bool valid = (grow < B);

    // ---- Init: z0 = zm + exp(0.5*lv)*eps into Xs; density from lv & eps.
    {
        float4 zm4 = make_float4(0.f, 0.f, 0.f, 0.f);
        float4 lv4 = zm4, e4 = zm4;
        if (valid) {
            zm4 = *(const float4*)(zm  + (size_t)grow * 64 + j0);
            lv4 = *(const float4*)(lvp + (size_t)grow * 64 + j0);
            e4  = *(const float4*)(ep  + (size_t)grow * 64 + j0);
        }
        float zx = zm4.x + expf(0.5f * lv4.x) * e4.x;
        float zy = zm4.y + expf(0.5f * lv4.y) * e4.y;
        float zz = zm4.z + expf(0.5f * lv4.z) * e4.z;
        float zw = zm4.w + expf(0.5f * lv4.w) * e4.w;
        float* xr = Xs + r * XST;
        xr[j0 + 0] = zx; xr[j0 + 1] = zy; xr[j0 + 2] = zz; xr[j0 + 3] = zw;

        float slv = lv4.x + lv4.y + lv4.z + lv4.w;
        float se2 = e4.x * e4.x + e4.y * e4.y + e4.z * e4.z + e4.w * e4.w;
        #pragma unroll
        for (int off = 8; off; off >>= 1) {
            slv += __shfl_xor_sync(0xffffffffu, slv, off, 16);
            se2 += __shfl_xor_sync(0xffffffffu, se2, off, 16);
        }
        if (c == 0 && valid) {
            // -0.5*D*log(2*pi) with D=64
            float dens = -0.5f * 64.0f * 1.8378770664093453f - 0.5f * slv - 0.5f * se2;
            out[(size_t)B * 64 + grow] = dens;
        }
    }
    __syncthreads();

    // ---- Inverse pass: flow i=1 first, then i=0 (reverse between them).
    #pragma unroll
    for (int fi = 0; fi < 2; ++fi) {
        const int f = 1 - fi;                       // weight set to use
        const float* wbase = wts + f * 4 * 4096;
        const float* bbase = bss + f * 4 * 64;

        // 3 hidden layers with relu: Xs->Ha->Hb->Ha
        const float* IN  = Xs;
        float*       OUT = Ha;
        #pragma unroll
        for (int l = 0; l < 3; ++l) {
            const float* W  = wbase + l * 4096;
            const float* bb = bbase + l * 64;
            float a0 = bb[j0 + 0], a1 = bb[j0 + 1], a2 = bb[j0 + 2], a3 = bb[j0 + 3];
            const float* inr = IN + r * XST;
            #pragma unroll
            for (int d = 0; d < 64; ++d) {
                float  x = inr[d];
                float4 w = *(const float4*)(W + d * 64 + j0);
                a0 = fmaf(x, w.x, a0);
                a1 = fmaf(x, w.y, a1);
                a2 = fmaf(x, w.z, a2);
                a3 = fmaf(x, w.w, a3);
            }
            float* outr = OUT + r * XST;
            outr[j0 + 0] = fmaxf(a0, 0.f);
            outr[j0 + 1] = fmaxf(a1, 0.f);
            outr[j0 + 2] = fmaxf(a2, 0.f);
            outr[j0 + 3] = fmaxf(a3, 0.f);
            __syncthreads();
            IN  = OUT;
            OUT = (l == 0) ? Hb : Ha;
        }

        // Output layer (no relu): z_new = z - (h3 @ Woutm + bout)
        {
            const float* W  = wbase + 3 * 4096;
            const float* bb = bbase + 3 * 64;
            float a0 = bb[j0 + 0], a1 = bb[j0 + 1], a2 = bb[j0 + 2], a3 = bb[j0 + 3];
            const float* inr = Ha + r * XST;   // final hidden lives in Ha
            #pragma unroll
            for (int d = 0; d < 64; ++d) {
                float  x = inr[d];
                float4 w = *(const float4*)(W + d * 64 + j0);
                a0 = fmaf(x, w.x, a0);
                a1 = fmaf(x, w.y, a1);
                a2 = fmaf(x, w.z, a2);
                a3 = fmaf(x, w.w, a3);
            }
            float* xr = Xs + r * XST;
            float zn0 = xr[j0 + 0] - a0;
            float zn1 = xr[j0 + 1] - a1;
            float zn2 = xr[j0 + 2] - a2;
            float zn3 = xr[j0 + 3] - a3;
            __syncthreads();                   // everyone done reading Xs
            if (fi == 0) {
                // reverse along D while writing back
                xr[63 - (j0 + 0)] = zn0;
                xr[63 - (j0 + 1)] = zn1;
                xr[63 - (j0 + 2)] = zn2;
                xr[63 - (j0 + 3)] = zn3;
            } else if (valid) {
                *(float4*)(out + (size_t)grow * 64 + j0) = make_float4(zn0, zn1, zn2, zn3);
            }
            __syncthreads();
        }
    }
}

extern "C" void kernel_launch(void* const* d_in, const int* in_sizes, int n_in,
                              void* d_out, int out_size) {
    const float* zm = (const float*)d_in[0];
    const float* lv = (const float*)d_in[1];
    const float* ep = (const float*)d_in[2];
    const float* W0 = (const float*)d_in[3];
    const float* b0 = (const float*)d_in[4];
    const float* W1 = (const float*)d_in[5];
    const float* b1 = (const float*)d_in[6];
    const float* W2 = (const float*)d_in[7];
    const float* b2 = (const float*)d_in[8];
    const float* Wo = (const float*)d_in[9];
    const float* bo = (const float*)d_in[10];

    int B = in_sizes[0] / 64;

    int smem = (8 * 4096 + 8 * 64 + 3 * RB * XST) * (int)sizeof(float);  // 159232 B
    cudaFuncSetAttribute(iaf_kernel, cudaFuncAttributeMaxDynamicSharedMemorySize, smem);

    int grid = (B + RB - 1) / RB;
    iaf_kernel<<<grid, NT, smem>>>(zm, lv, ep, W0, b0, W1, b1, W2, b2, Wo, bo,
                                   (float*)d_out, B);
}